// round 7
// baseline (speedup 1.0000x reference)
#include <cuda_runtime.h>
#include <cuda_bf16.h>

// values[m] = sum_n exp(-0.5 * sum_d (p[m,d]-pos[n,d])^2 / (exp(ls[n,d])^2+eps)) * I[n]
//
// Log2-domain expansion per gaussian n:
//   civ_d = -0.5*log2(e)/(exp(ls_d)^2+eps);  a_d=civ_d; b_d=-2*civ_d*s_d
//   cc = sum_d civ_d*s_d^2 + log2(I);  arg = sum_d (a_d*p_d^2 + b_d*p_d) + cc
//   contribution = exp2(arg)
//
// Two gaussians per FFMA2 lane (point value broadcast to both lanes),
// two points per thread sharing each coefficient load (4 LDS -> 4 evals).
// Segments across blockIdx.y (1/8 of the gaussians, 4KB smem slice per block,
// recomputed in-block: 64 pairs, trivial). Partials combined via atomicAdd
// into a memset-zeroed output.
//
// Round 7: block 128 (was 256) -> 1568 total blocks, ~10.6 blocks/SM in a
// single balanced wave (reg cap 12/SM); unroll 8 to amortize loop ALU.

#define SEGS 8
#define BLOCK_THREADS 128
#define PTS_PER_BLOCK (2 * BLOCK_THREADS)    // 256

__device__ __forceinline__ unsigned long long ffma2(unsigned long long a,
                                                    unsigned long long b,
                                                    unsigned long long c) {
    unsigned long long d;
    asm("fma.rn.f32x2 %0, %1, %2, %3;" : "=l"(d) : "l"(a), "l"(b), "l"(c));
    return d;
}
__device__ __forceinline__ unsigned long long addx2(unsigned long long a,
                                                    unsigned long long b) {
    unsigned long long d;
    asm("add.rn.f32x2 %0, %1, %2;" : "=l"(d) : "l"(a), "l"(b));
    return d;
}
__device__ __forceinline__ unsigned long long pack2(float lo, float hi) {
    unsigned long long d;
    asm("mov.b64 %0, {%1, %2};" : "=l"(d) : "f"(lo), "f"(hi));
    return d;
}
__device__ __forceinline__ float pair_hsum(unsigned long long v) {
    float lo, hi;
    asm("mov.b64 {%0, %1}, %2;" : "=f"(lo), "=f"(hi) : "l"(v));
    return lo + hi;
}
__device__ __forceinline__ void unpack2(unsigned long long v, float& lo, float& hi) {
    asm("mov.b64 {%0, %1}, %2;" : "=f"(lo), "=f"(hi) : "l"(v));
}
__device__ __forceinline__ float ex2(float x) {
    float r;
    asm("ex2.approx.f32 %0, %1;" : "=f"(r) : "f"(x));
    return r;
}

__global__ void __launch_bounds__(BLOCK_THREADS)
eval_kernel(const float* __restrict__ points,
            const float* __restrict__ positions,
            const float* __restrict__ log_scales,
            const float* __restrict__ intensities,
            float* __restrict__ out,
            int M, int N) {
    extern __shared__ float4 sp4[];          // pairsPerSeg * 4 float4 (4KB @ N=1024)
    int pairsPerSeg = (N / 2) / SEGS;        // 64
    int seg = blockIdx.y;

    // ---- build this segment's coefficient slice ----
    const float LOG2E = 1.4426950408889634f;
    for (int t = threadIdx.x; t < pairsPerSeg; t += BLOCK_THREADS) {
        int j = seg * pairsPerSeg + t;
        float a[2][3], b[2][3], cc[2];
#pragma unroll
        for (int k = 0; k < 2; k++) {
            int n = 2 * j + k;
            float c = 0.0f;
#pragma unroll
            for (int d = 0; d < 3; d++) {
                float s = __expf(log_scales[3 * n + d]);
                float civ = -0.5f * LOG2E / (s * s + 1e-6f);
                float p = positions[3 * n + d];
                a[k][d] = civ;
                b[k][d] = -2.0f * civ * p;
                c = fmaf(civ, p * p, c);
            }
            cc[k] = c + __log2f(intensities[n]);  // I=0 -> -inf -> exp2 -> 0
        }
        sp4[4 * t + 0] = make_float4(a[0][0], a[1][0], a[0][1], a[1][1]); // ax|ay
        sp4[4 * t + 1] = make_float4(a[0][2], a[1][2], b[0][0], b[1][0]); // az|bx
        sp4[4 * t + 2] = make_float4(b[0][1], b[1][1], b[0][2], b[1][2]); // by|bz
        sp4[4 * t + 3] = make_float4(cc[0], cc[1], 0.0f, 0.0f);           // cc
    }
    __syncthreads();

    // ---- main loop: 2 points per thread over this segment's pairs ----
    int m0 = blockIdx.x * PTS_PER_BLOCK + threadIdx.x;
    int m1 = m0 + BLOCK_THREADS;

    float px0 = 0.f, py0 = 0.f, pz0 = 0.f, px1 = 0.f, py1 = 0.f, pz1 = 0.f;
    if (m0 < M) { px0 = points[3*m0]; py0 = points[3*m0+1]; pz0 = points[3*m0+2]; }
    if (m1 < M) { px1 = points[3*m1]; py1 = points[3*m1+1]; pz1 = points[3*m1+2]; }

    unsigned long long vxx0 = pack2(px0*px0, px0*px0), vx0 = pack2(px0, px0);
    unsigned long long vyy0 = pack2(py0*py0, py0*py0), vy0 = pack2(py0, py0);
    unsigned long long vzz0 = pack2(pz0*pz0, pz0*pz0), vz0 = pack2(pz0, pz0);
    unsigned long long vxx1 = pack2(px1*px1, px1*px1), vx1 = pack2(px1, px1);
    unsigned long long vyy1 = pack2(py1*py1, py1*py1), vy1 = pack2(py1, py1);
    unsigned long long vzz1 = pack2(pz1*pz1, pz1*pz1), vz1 = pack2(pz1, pz1);

    const ulonglong2* g = (const ulonglong2*)sp4;
    unsigned long long acc0 = pack2(0.0f, 0.0f);
    unsigned long long acc1 = pack2(0.0f, 0.0f);

#pragma unroll 8
    for (int j = 0; j < pairsPerSeg; j++) {
        ulonglong2 u0 = g[4 * j + 0];    // ax01 | ay01
        ulonglong2 u1 = g[4 * j + 1];    // az01 | bx01
        ulonglong2 u2 = g[4 * j + 2];    // by01 | bz01
        unsigned long long cc01 = *((const unsigned long long*)(g + 4 * j + 3));

        unsigned long long r0 = ffma2(u0.x, vxx0, cc01);
        unsigned long long r1 = ffma2(u0.x, vxx1, cc01);
        r0 = ffma2(u0.y, vyy0, r0);
        r1 = ffma2(u0.y, vyy1, r1);
        r0 = ffma2(u1.x, vzz0, r0);
        r1 = ffma2(u1.x, vzz1, r1);
        r0 = ffma2(u1.y, vx0,  r0);
        r1 = ffma2(u1.y, vx1,  r1);
        r0 = ffma2(u2.x, vy0,  r0);
        r1 = ffma2(u2.x, vy1,  r1);
        r0 = ffma2(u2.y, vz0,  r0);
        r1 = ffma2(u2.y, vz1,  r1);

        float lo0, hi0, lo1, hi1;
        unpack2(r0, lo0, hi0);
        unpack2(r1, lo1, hi1);
        acc0 = addx2(acc0, pack2(ex2(lo0), ex2(hi0)));
        acc1 = addx2(acc1, pack2(ex2(lo1), ex2(hi1)));
    }

    if (m0 < M) atomicAdd(&out[m0], pair_hsum(acc0));
    if (m1 < M) atomicAdd(&out[m1], pair_hsum(acc1));
}

extern "C" void kernel_launch(void* const* d_in, const int* in_sizes, int n_in,
                              void* d_out, int out_size) {
    const float* points      = (const float*)d_in[0];  // [M,3]
    const float* positions   = (const float*)d_in[1];  // [N,3]
    const float* log_scales  = (const float*)d_in[2];  // [N,3]
    const float* intensities = (const float*)d_in[3];  // [N]
    float* out = (float*)d_out;

    int M = in_sizes[0] / 3;
    int N = in_sizes[3];

    cudaMemsetAsync(out, 0, (size_t)out_size * sizeof(float));

    dim3 grid((M + PTS_PER_BLOCK - 1) / PTS_PER_BLOCK, SEGS);
    size_t smem = (size_t)((N / 2) / SEGS) * 4 * sizeof(float4);
    eval_kernel<<<grid, BLOCK_THREADS, smem>>>(points, positions, log_scales,
                                               intensities, out, M, N);
}

// round 8
// speedup vs baseline: 1.4413x; 1.4413x over previous
#include <cuda_runtime.h>
#include <cuda_bf16.h>

// values[m] = sum_n exp(-0.5 * sum_d (p[m,d]-pos[n,d])^2 / (exp(ls[n,d])^2+eps)) * I[n]
//
// Log2-domain expansion per gaussian n:
//   civ_d = -0.5*log2(e)/(exp(ls_d)^2+eps);  a_d=civ_d; b_d=-2*civ_d*s_d
//   cc = sum_d civ_d*s_d^2 + log2(I);  arg = sum_d (a_d*p_d^2 + b_d*p_d) + cc
//   contribution = exp2(arg)
//
// Two gaussians per FFMA2 lane (point value broadcast to both lanes),
// two points per thread sharing each coefficient load (4 LDS -> 4 evals).
// Segments across blockIdx.y (1/8 of gaussians). Coefficients prepared ONCE
// by a tiny prep kernel; each eval block copies its 4KB slice global->smem.
// Partials combined via atomicAdd into memset-zeroed output.

#define MAX_N 4096
__device__ float4 g_pairs[2 * MAX_N];    // 4 float4 per gaussian-pair

#define SEGS 8
#define BLOCK_THREADS 256
#define PTS_PER_BLOCK (2 * BLOCK_THREADS)    // 512

__global__ void prep_kernel(const float* __restrict__ positions,
                            const float* __restrict__ log_scales,
                            const float* __restrict__ intensities,
                            int N) {
    int j = blockIdx.x * blockDim.x + threadIdx.x;
    if (j >= N / 2) return;
    const float LOG2E = 1.4426950408889634f;
    float a[2][3], b[2][3], cc[2];
#pragma unroll
    for (int k = 0; k < 2; k++) {
        int n = 2 * j + k;
        float c = 0.0f;
#pragma unroll
        for (int d = 0; d < 3; d++) {
            float s = __expf(log_scales[3 * n + d]);
            float civ = -0.5f * LOG2E / (s * s + 1e-6f);
            float p = positions[3 * n + d];
            a[k][d] = civ;
            b[k][d] = -2.0f * civ * p;
            c = fmaf(civ, p * p, c);
        }
        cc[k] = c + __log2f(intensities[n]);   // I=0 -> -inf -> exp2 -> 0, correct
    }
    g_pairs[4 * j + 0] = make_float4(a[0][0], a[1][0], a[0][1], a[1][1]); // ax|ay
    g_pairs[4 * j + 1] = make_float4(a[0][2], a[1][2], b[0][0], b[1][0]); // az|bx
    g_pairs[4 * j + 2] = make_float4(b[0][1], b[1][1], b[0][2], b[1][2]); // by|bz
    g_pairs[4 * j + 3] = make_float4(cc[0], cc[1], 0.0f, 0.0f);           // cc
}

__device__ __forceinline__ unsigned long long ffma2(unsigned long long a,
                                                    unsigned long long b,
                                                    unsigned long long c) {
    unsigned long long d;
    asm("fma.rn.f32x2 %0, %1, %2, %3;" : "=l"(d) : "l"(a), "l"(b), "l"(c));
    return d;
}
__device__ __forceinline__ unsigned long long addx2(unsigned long long a,
                                                    unsigned long long b) {
    unsigned long long d;
    asm("add.rn.f32x2 %0, %1, %2;" : "=l"(d) : "l"(a), "l"(b));
    return d;
}
__device__ __forceinline__ unsigned long long pack2(float lo, float hi) {
    unsigned long long d;
    asm("mov.b64 %0, {%1, %2};" : "=l"(d) : "f"(lo), "f"(hi));
    return d;
}
__device__ __forceinline__ float pair_hsum(unsigned long long v) {
    float lo, hi;
    asm("mov.b64 {%0, %1}, %2;" : "=f"(lo), "=f"(hi) : "l"(v));
    return lo + hi;
}
__device__ __forceinline__ void unpack2(unsigned long long v, float& lo, float& hi) {
    asm("mov.b64 {%0, %1}, %2;" : "=f"(lo), "=f"(hi) : "l"(v));
}
__device__ __forceinline__ float ex2(float x) {
    float r;
    asm("ex2.approx.f32 %0, %1;" : "=f"(r) : "f"(x));
    return r;
}

__global__ void __launch_bounds__(BLOCK_THREADS)
eval_kernel(const float* __restrict__ points,
            float* __restrict__ out,
            int M, int N) {
    extern __shared__ float4 sp4[];          // pairsPerSeg * 4 float4 (4KB @ N=1024)
    const int pairsPerSeg = (N / 2) / SEGS;  // 64
    int seg = blockIdx.y;

    // copy this segment's 4KB coefficient slice (1 float4 per thread)
    {
        const float4* src = g_pairs + (size_t)seg * pairsPerSeg * 4;
        for (int i = threadIdx.x; i < pairsPerSeg * 4; i += BLOCK_THREADS)
            sp4[i] = src[i];
    }
    __syncthreads();

    int m0 = blockIdx.x * PTS_PER_BLOCK + threadIdx.x;
    int m1 = m0 + BLOCK_THREADS;

    float px0 = 0.f, py0 = 0.f, pz0 = 0.f, px1 = 0.f, py1 = 0.f, pz1 = 0.f;
    if (m0 < M) { px0 = points[3*m0]; py0 = points[3*m0+1]; pz0 = points[3*m0+2]; }
    if (m1 < M) { px1 = points[3*m1]; py1 = points[3*m1+1]; pz1 = points[3*m1+2]; }

    unsigned long long vxx0 = pack2(px0*px0, px0*px0), vx0 = pack2(px0, px0);
    unsigned long long vyy0 = pack2(py0*py0, py0*py0), vy0 = pack2(py0, py0);
    unsigned long long vzz0 = pack2(pz0*pz0, pz0*pz0), vz0 = pack2(pz0, pz0);
    unsigned long long vxx1 = pack2(px1*px1, px1*px1), vx1 = pack2(px1, px1);
    unsigned long long vyy1 = pack2(py1*py1, py1*py1), vy1 = pack2(py1, py1);
    unsigned long long vzz1 = pack2(pz1*pz1, pz1*pz1), vz1 = pack2(pz1, pz1);

    const ulonglong2* g = (const ulonglong2*)sp4;
    unsigned long long acc0 = pack2(0.0f, 0.0f);
    unsigned long long acc1 = pack2(0.0f, 0.0f);

#pragma unroll 16
    for (int j = 0; j < 64; j++) {           // pairsPerSeg is compile-time 64 @ N=1024
        ulonglong2 u0 = g[4 * j + 0];        // ax01 | ay01
        ulonglong2 u1 = g[4 * j + 1];        // az01 | bx01
        ulonglong2 u2 = g[4 * j + 2];        // by01 | bz01
        unsigned long long cc01 = *((const unsigned long long*)(g + 4 * j + 3));

        unsigned long long r0 = ffma2(u0.x, vxx0, cc01);
        unsigned long long r1 = ffma2(u0.x, vxx1, cc01);
        r0 = ffma2(u0.y, vyy0, r0);
        r1 = ffma2(u0.y, vyy1, r1);
        r0 = ffma2(u1.x, vzz0, r0);
        r1 = ffma2(u1.x, vzz1, r1);
        r0 = ffma2(u1.y, vx0,  r0);
        r1 = ffma2(u1.y, vx1,  r1);
        r0 = ffma2(u2.x, vy0,  r0);
        r1 = ffma2(u2.x, vy1,  r1);
        r0 = ffma2(u2.y, vz0,  r0);
        r1 = ffma2(u2.y, vz1,  r1);

        float lo0, hi0, lo1, hi1;
        unpack2(r0, lo0, hi0);
        unpack2(r1, lo1, hi1);
        acc0 = addx2(acc0, pack2(ex2(lo0), ex2(hi0)));
        acc1 = addx2(acc1, pack2(ex2(lo1), ex2(hi1)));
    }

    if (m0 < M) atomicAdd(&out[m0], pair_hsum(acc0));
    if (m1 < M) atomicAdd(&out[m1], pair_hsum(acc1));
}

extern "C" void kernel_launch(void* const* d_in, const int* in_sizes, int n_in,
                              void* d_out, int out_size) {
    const float* points      = (const float*)d_in[0];  // [M,3]
    const float* positions   = (const float*)d_in[1];  // [N,3]
    const float* log_scales  = (const float*)d_in[2];  // [N,3]
    const float* intensities = (const float*)d_in[3];  // [N]
    float* out = (float*)d_out;

    int M = in_sizes[0] / 3;
    int N = in_sizes[3];

    cudaMemsetAsync(out, 0, (size_t)out_size * sizeof(float));

    prep_kernel<<<(N / 2 + 255) / 256, 256>>>(positions, log_scales, intensities, N);

    dim3 grid((M + PTS_PER_BLOCK - 1) / PTS_PER_BLOCK, SEGS);
    size_t smem = (size_t)((N / 2) / SEGS) * 4 * sizeof(float4);
    eval_kernel<<<grid, BLOCK_THREADS, smem>>>(points, out, M, N);
}

// round 9
// speedup vs baseline: 1.5483x; 1.0743x over previous
#include <cuda_runtime.h>
#include <cuda_bf16.h>

// values[m] = sum_n exp(-0.5 * sum_d (p[m,d]-pos[n,d])^2 / (exp(ls[n,d])^2+eps)) * I[n]
//
// Log2-domain expansion per gaussian n:
//   civ_d = -0.5*log2(e)/(exp(ls_d)^2+eps);  a_d=civ_d; b_d=-2*civ_d*s_d
//   cc = sum_d civ_d*s_d^2 + log2(I);  arg = sum_d (a_d*p_d^2 + b_d*p_d) + cc
//   contribution = exp2(arg)
//
// Two gaussians per FFMA2 lane (point values broadcast into both lanes),
// two points per thread sharing each coefficient load (4 LDS -> 4 evals).
// Gaussian list split across blockIdx.y (SEGS=8); each eval block COPIES its
// 4KB slice from the precomputed global table (no per-block recompute).
// Partials combined via atomicAdd into an output zeroed by the prep kernel.
//
// R9 schedule: block=128, 256 pts/block -> grid 196x8=1568 blocks, 42 regs
// -> 12-block/SM reg cap -> single balanced wave at ~10.6 blocks/SM.

#define MAX_N 4096
__device__ float4 g_pairs[2 * MAX_N];    // 4 float4 per gaussian-pair

#define SEGS 8
#define BLOCK_THREADS 128
#define PTS_PER_BLOCK (2 * BLOCK_THREADS)    // 256

// One launch: zero the output AND build the pair-packed coefficient table.
__global__ void prep_kernel(const float* __restrict__ positions,
                            const float* __restrict__ log_scales,
                            const float* __restrict__ intensities,
                            float* __restrict__ out,
                            int out_elems, int N) {
    int idx = blockIdx.x * blockDim.x + threadIdx.x;
    if (idx < out_elems) out[idx] = 0.0f;

    int j = idx;
    if (j < N / 2) {
        const float LOG2E = 1.4426950408889634f;
        float a[2][3], b[2][3], cc[2];
#pragma unroll
        for (int k = 0; k < 2; k++) {
            int n = 2 * j + k;
            float c = 0.0f;
#pragma unroll
            for (int d = 0; d < 3; d++) {
                float s = __expf(log_scales[3 * n + d]);
                float civ = -0.5f * LOG2E / (s * s + 1e-6f);
                float p = positions[3 * n + d];
                a[k][d] = civ;
                b[k][d] = -2.0f * civ * p;
                c = fmaf(civ, p * p, c);
            }
            cc[k] = c + __log2f(intensities[n]);  // I=0 -> -inf -> exp2 -> 0, correct
        }
        g_pairs[4 * j + 0] = make_float4(a[0][0], a[1][0], a[0][1], a[1][1]); // ax|ay
        g_pairs[4 * j + 1] = make_float4(a[0][2], a[1][2], b[0][0], b[1][0]); // az|bx
        g_pairs[4 * j + 2] = make_float4(b[0][1], b[1][1], b[0][2], b[1][2]); // by|bz
        g_pairs[4 * j + 3] = make_float4(cc[0], cc[1], 0.0f, 0.0f);           // cc
    }
}

__device__ __forceinline__ unsigned long long ffma2(unsigned long long a,
                                                    unsigned long long b,
                                                    unsigned long long c) {
    unsigned long long d;
    asm("fma.rn.f32x2 %0, %1, %2, %3;" : "=l"(d) : "l"(a), "l"(b), "l"(c));
    return d;
}
__device__ __forceinline__ unsigned long long addx2(unsigned long long a,
                                                    unsigned long long b) {
    unsigned long long d;
    asm("add.rn.f32x2 %0, %1, %2;" : "=l"(d) : "l"(a), "l"(b));
    return d;
}
__device__ __forceinline__ unsigned long long pack2(float lo, float hi) {
    unsigned long long d;
    asm("mov.b64 %0, {%1, %2};" : "=l"(d) : "f"(lo), "f"(hi));
    return d;
}
__device__ __forceinline__ float pair_hsum(unsigned long long v) {
    float lo, hi;
    asm("mov.b64 {%0, %1}, %2;" : "=f"(lo), "=f"(hi) : "l"(v));
    return lo + hi;
}
__device__ __forceinline__ void unpack2(unsigned long long v, float& lo, float& hi) {
    asm("mov.b64 {%0, %1}, %2;" : "=f"(lo), "=f"(hi) : "l"(v));
}
__device__ __forceinline__ float ex2(float x) {
    float r;
    asm("ex2.approx.f32 %0, %1;" : "=f"(r) : "f"(x));
    return r;
}

__global__ void __launch_bounds__(BLOCK_THREADS)
eval_kernel(const float* __restrict__ points,
            float* __restrict__ out,
            int M, int N) {
    extern __shared__ float4 sp4[];          // pairsPerSeg * 4 float4 (4KB @ N=1024)
    const int pairsPerSeg = (N / 2) / SEGS;  // 64
    int seg = blockIdx.y;

    // copy this segment's 4KB coefficient slice (2 float4 per thread)
    {
        const float4* src = g_pairs + (size_t)seg * pairsPerSeg * 4;
        for (int i = threadIdx.x; i < pairsPerSeg * 4; i += BLOCK_THREADS)
            sp4[i] = src[i];
    }
    __syncthreads();

    int m0 = blockIdx.x * PTS_PER_BLOCK + threadIdx.x;
    int m1 = m0 + BLOCK_THREADS;

    float px0 = 0.f, py0 = 0.f, pz0 = 0.f, px1 = 0.f, py1 = 0.f, pz1 = 0.f;
    if (m0 < M) { px0 = points[3*m0]; py0 = points[3*m0+1]; pz0 = points[3*m0+2]; }
    if (m1 < M) { px1 = points[3*m1]; py1 = points[3*m1+1]; pz1 = points[3*m1+2]; }

    unsigned long long vxx0 = pack2(px0*px0, px0*px0), vx0 = pack2(px0, px0);
    unsigned long long vyy0 = pack2(py0*py0, py0*py0), vy0 = pack2(py0, py0);
    unsigned long long vzz0 = pack2(pz0*pz0, pz0*pz0), vz0 = pack2(pz0, pz0);
    unsigned long long vxx1 = pack2(px1*px1, px1*px1), vx1 = pack2(px1, px1);
    unsigned long long vyy1 = pack2(py1*py1, py1*py1), vy1 = pack2(py1, py1);
    unsigned long long vzz1 = pack2(pz1*pz1, pz1*pz1), vz1 = pack2(pz1, pz1);

    const ulonglong2* g = (const ulonglong2*)sp4;
    unsigned long long acc0 = pack2(0.0f, 0.0f);
    unsigned long long acc1 = pack2(0.0f, 0.0f);

#pragma unroll 16
    for (int j = 0; j < 64; j++) {           // pairsPerSeg == 64 @ N=1024
        ulonglong2 u0 = g[4 * j + 0];        // ax01 | ay01
        ulonglong2 u1 = g[4 * j + 1];        // az01 | bx01
        ulonglong2 u2 = g[4 * j + 2];        // by01 | bz01
        unsigned long long cc01 = *((const unsigned long long*)(g + 4 * j + 3));

        unsigned long long r0 = ffma2(u0.x, vxx0, cc01);
        unsigned long long r1 = ffma2(u0.x, vxx1, cc01);
        r0 = ffma2(u0.y, vyy0, r0);
        r1 = ffma2(u0.y, vyy1, r1);
        r0 = ffma2(u1.x, vzz0, r0);
        r1 = ffma2(u1.x, vzz1, r1);
        r0 = ffma2(u1.y, vx0,  r0);
        r1 = ffma2(u1.y, vx1,  r1);
        r0 = ffma2(u2.x, vy0,  r0);
        r1 = ffma2(u2.x, vy1,  r1);
        r0 = ffma2(u2.y, vz0,  r0);
        r1 = ffma2(u2.y, vz1,  r1);

        float lo0, hi0, lo1, hi1;
        unpack2(r0, lo0, hi0);
        unpack2(r1, lo1, hi1);
        acc0 = addx2(acc0, pack2(ex2(lo0), ex2(hi0)));
        acc1 = addx2(acc1, pack2(ex2(lo1), ex2(hi1)));
    }

    if (m0 < M) atomicAdd(&out[m0], pair_hsum(acc0));
    if (m1 < M) atomicAdd(&out[m1], pair_hsum(acc1));
}

extern "C" void kernel_launch(void* const* d_in, const int* in_sizes, int n_in,
                              void* d_out, int out_size) {
    const float* points      = (const float*)d_in[0];  // [M,3]
    const float* positions   = (const float*)d_in[1];  // [N,3]
    const float* log_scales  = (const float*)d_in[2];  // [N,3]
    const float* intensities = (const float*)d_in[3];  // [N]
    float* out = (float*)d_out;

    int M = in_sizes[0] / 3;
    int N = in_sizes[3];

    int prepGrid = (out_size + 255) / 256;   // covers zeroing (and N/2 pairs)
    prep_kernel<<<prepGrid, 256>>>(positions, log_scales, intensities,
                                   out, out_size, N);

    dim3 grid((M + PTS_PER_BLOCK - 1) / PTS_PER_BLOCK, SEGS);
    size_t smem = (size_t)((N / 2) / SEGS) * 4 * sizeof(float4);
    eval_kernel<<<grid, BLOCK_THREADS, smem>>>(points, out, M, N);
}